// round 2
// baseline (speedup 1.0000x reference)
#include <cuda_runtime.h>
#include <cuda_bf16.h>
#include <mma.h>
#include <cstdint>

using namespace nvcuda;

#define NROWS 8192
#define DIM   2048
#define VOCAB 32000
#define TOPK  5
#define CAND  16
#define ALPHA 0.5f
#define TEMP  10.0f

// ---------------- device scratch (static globals: allocation-free) ----------
__device__ __nv_bfloat16 g_embb[(size_t)NROWS * DIM];          // raw emb, bf16
__device__ __nv_bfloat16 g_vocb[(size_t)VOCAB * DIM];          // vocab * inv_norm, bf16
__device__ __nv_bfloat16 g_sim [(size_t)NROWS * VOCAB];        // sim matrix, bf16
__device__ float g_emb_inv[NROWS];
__device__ float g_voc_inv[VOCAB];
__device__ int   g_cand[NROWS * CAND];

// ---------------- prep: norms + bf16 conversion -----------------------------
__global__ void __launch_bounds__(256) prep_emb_kernel(const float* __restrict__ emb) {
    int row = blockIdx.x;
    int t = threadIdx.x;
    const float4* s4 = (const float4*)(emb + (size_t)row * DIM);
    float4 a = s4[t * 2], b = s4[t * 2 + 1];
    float ss = a.x*a.x + a.y*a.y + a.z*a.z + a.w*a.w
             + b.x*b.x + b.y*b.y + b.z*b.z + b.w*b.w;
    __shared__ float red[256];
    red[t] = ss; __syncthreads();
    for (int o = 128; o > 0; o >>= 1) { if (t < o) red[t] += red[t + o]; __syncthreads(); }
    if (t == 0) g_emb_inv[row] = 1.0f / fmaxf(sqrtf(red[0]), 1e-12f);
    __nv_bfloat162* d2 = (__nv_bfloat162*)(g_embb + (size_t)row * DIM + t * 8);
    d2[0] = __floats2bfloat162_rn(a.x, a.y);
    d2[1] = __floats2bfloat162_rn(a.z, a.w);
    d2[2] = __floats2bfloat162_rn(b.x, b.y);
    d2[3] = __floats2bfloat162_rn(b.z, b.w);
}

__global__ void __launch_bounds__(256) prep_voc_kernel(const float* __restrict__ voc) {
    int row = blockIdx.x;
    int t = threadIdx.x;
    const float4* s4 = (const float4*)(voc + (size_t)row * DIM);
    float4 a = s4[t * 2], b = s4[t * 2 + 1];
    float ss = a.x*a.x + a.y*a.y + a.z*a.z + a.w*a.w
             + b.x*b.x + b.y*b.y + b.z*b.z + b.w*b.w;
    __shared__ float red[256];
    __shared__ float s_inv;
    red[t] = ss; __syncthreads();
    for (int o = 128; o > 0; o >>= 1) { if (t < o) red[t] += red[t + o]; __syncthreads(); }
    if (t == 0) {
        float inv = 1.0f / fmaxf(sqrtf(red[0]), 1e-12f);
        g_voc_inv[row] = inv;
        s_inv = inv;
    }
    __syncthreads();
    float inv = s_inv;
    __nv_bfloat162* d2 = (__nv_bfloat162*)(g_vocb + (size_t)row * DIM + t * 8);
    d2[0] = __floats2bfloat162_rn(a.x * inv, a.y * inv);
    d2[1] = __floats2bfloat162_rn(a.z * inv, a.w * inv);
    d2[2] = __floats2bfloat162_rn(b.x * inv, b.y * inv);
    d2[3] = __floats2bfloat162_rn(b.z * inv, b.w * inv);
}

// ---------------- GEMM: sim = embb @ vocb^T (bf16 in, f32 acc, bf16 out) ----
// Block tile 128x128, 8 warps (2x4), warp tile 64x32, k-step 32.
#define BK   32
#define KPAD 40

__global__ void __launch_bounds__(256) sim_gemm_kernel() {
    __shared__ __nv_bfloat16 As[128 * KPAD];
    __shared__ __nv_bfloat16 Bs[128 * KPAD];
    __shared__ float stage[8 * 256];

    int tid  = threadIdx.x;
    int lane = tid & 31;
    int wid  = tid >> 5;
    int warp_m = wid >> 2;   // 0..1
    int warp_n = wid & 3;    // 0..3
    int rowbase = blockIdx.x * 128;
    int colbase = blockIdx.y * 128;

    wmma::fragment<wmma::accumulator, 16, 16, 16, float> c[4][2];
    #pragma unroll
    for (int i = 0; i < 4; i++)
        #pragma unroll
        for (int j = 0; j < 2; j++)
            wmma::fill_fragment(c[i][j], 0.0f);

    for (int kt = 0; kt < DIM; kt += BK) {
        #pragma unroll
        for (int q = 0; q < 2; q++) {
            int idx = tid + q * 256;          // 0..511 (chunks of 8 bf16)
            int r  = idx >> 2;
            int cb = (idx & 3) * 8;
            *(uint4*)(As + r * KPAD + cb) =
                *(const uint4*)(g_embb + (size_t)(rowbase + r) * DIM + kt + cb);
            *(uint4*)(Bs + r * KPAD + cb) =
                *(const uint4*)(g_vocb + (size_t)(colbase + r) * DIM + kt + cb);
        }
        __syncthreads();
        #pragma unroll
        for (int kk = 0; kk < 2; kk++) {
            wmma::fragment<wmma::matrix_a, 16, 16, 16, __nv_bfloat16, wmma::row_major> a[4];
            wmma::fragment<wmma::matrix_b, 16, 16, 16, __nv_bfloat16, wmma::col_major> b[2];
            #pragma unroll
            for (int i = 0; i < 4; i++)
                wmma::load_matrix_sync(a[i], As + (warp_m * 64 + i * 16) * KPAD + kk * 16, KPAD);
            #pragma unroll
            for (int j = 0; j < 2; j++)
                wmma::load_matrix_sync(b[j], Bs + (warp_n * 32 + j * 16) * KPAD + kk * 16, KPAD);
            #pragma unroll
            for (int i = 0; i < 4; i++)
                #pragma unroll
                for (int j = 0; j < 2; j++)
                    wmma::mma_sync(c[i][j], a[i], b[j], c[i][j]);
        }
        __syncthreads();
    }

    // epilogue: f32 frag -> smem -> bf16 global
    float* st = stage + wid * 256;
    #pragma unroll
    for (int i = 0; i < 4; i++) {
        #pragma unroll
        for (int j = 0; j < 2; j++) {
            wmma::store_matrix_sync(st, c[i][j], 16, wmma::mem_row_major);
            __syncwarp();
            #pragma unroll
            for (int u = 0; u < 8; u++) {
                int e  = lane * 8 + u;
                int r  = e >> 4;
                int cc = e & 15;
                int gr = rowbase + warp_m * 64 + i * 16 + r;
                int gc = colbase + warp_n * 32 + j * 16 + cc;
                g_sim[(size_t)gr * VOCAB + gc] = __float2bfloat16(st[e]);
            }
            __syncwarp();
        }
    }
}

// ---------------- top-16 candidates per row ---------------------------------
__global__ void __launch_bounds__(256) topm_kernel() {
    int row = blockIdx.x;
    int tid = threadIdx.x;
    const __nv_bfloat16* srow = g_sim + (size_t)row * VOCAB;

    float lv[CAND];
    int   li[CAND];
    #pragma unroll
    for (int i = 0; i < CAND; i++) { lv[i] = -1e30f; li[i] = -1; }

    for (int j = tid; j < VOCAB; j += 256) {
        float v = __bfloat162float(srow[j]);
        if (v > lv[CAND - 1]) {
            int p = CAND - 1;
            while (p > 0 && lv[p - 1] < v) {
                lv[p] = lv[p - 1]; li[p] = li[p - 1]; p--;
            }
            lv[p] = v; li[p] = j;
        }
    }

    __shared__ float sv[256 * CAND];
    __shared__ int   si[256 * CAND];
    #pragma unroll
    for (int i = 0; i < CAND; i++) { sv[tid * CAND + i] = lv[i]; si[tid * CAND + i] = li[i]; }
    __syncthreads();

    __shared__ float bv[256];
    __shared__ int   bvi[256];
    __shared__ int   bo[256];
    for (int k = 0; k < CAND; k++) {
        float best = -1e30f; int bi = 0x7fffffff; int bofs = 0;
        for (int e = tid; e < 256 * CAND; e += 256) {
            float v = sv[e]; int ii = si[e];
            if (v > best || (v == best && ii >= 0 && ii < bi)) { best = v; bi = ii; bofs = e; }
        }
        bv[tid] = best; bvi[tid] = bi; bo[tid] = bofs;
        __syncthreads();
        for (int o = 128; o > 0; o >>= 1) {
            if (tid < o) {
                if (bv[tid + o] > bv[tid] ||
                    (bv[tid + o] == bv[tid] && bvi[tid + o] < bvi[tid])) {
                    bv[tid] = bv[tid + o]; bvi[tid] = bvi[tid + o]; bo[tid] = bo[tid + o];
                }
            }
            __syncthreads();
        }
        if (tid == 0) {
            g_cand[row * CAND + k] = bvi[0];
            sv[bo[0]] = -1e30f;
        }
        __syncthreads();
    }
}

// ---------------- exact fp32 rescore + softmax + projection -----------------
__global__ void __launch_bounds__(256) rescore_out_kernel(
    const float* __restrict__ emb, const float* __restrict__ voc,
    float* __restrict__ out)
{
    int row  = blockIdx.x;
    int tid  = threadIdx.x;
    int lane = tid & 31;
    int wid  = tid >> 5;

    __shared__ float semb[DIM];
    const float4* e4 = (const float4*)(emb + (size_t)row * DIM);
    float4* s4 = (float4*)semb;
    for (int q = tid; q < DIM / 4; q += 256) s4[q] = e4[q];

    __shared__ int   cidx[CAND];
    __shared__ float csim[CAND];
    if (tid < CAND) cidx[tid] = g_cand[row * CAND + tid];
    __syncthreads();

    // 8 warps x 2 candidates: exact fp32 dot
    float inv_e = g_emb_inv[row];
    #pragma unroll
    for (int s = 0; s < 2; s++) {
        int c = wid * 2 + s;
        int v = cidx[c];
        const float4* vr = (const float4*)(voc + (size_t)v * DIM);
        float acc = 0.0f;
        for (int d = lane; d < DIM / 4; d += 32) {
            float4 a = s4[d];
            float4 b = vr[d];
            acc += a.x * b.x + a.y * b.y + a.z * b.z + a.w * b.w;
        }
        #pragma unroll
        for (int o = 16; o > 0; o >>= 1) acc += __shfl_xor_sync(0xffffffffu, acc, o);
        if (lane == 0) csim[c] = acc * inv_e * g_voc_inv[v];
    }
    __syncthreads();

    __shared__ float w5[TOPK];
    __shared__ int   i5[TOPK];
    if (tid == 0) {
        bool used[CAND];
        #pragma unroll
        for (int j = 0; j < CAND; j++) used[j] = false;
        float sv5[TOPK];
        for (int k = 0; k < TOPK; k++) {
            float best = -1e30f; int bj = -1; int bvix = 0x7fffffff;
            for (int j = 0; j < CAND; j++) {
                if (used[j]) continue;
                float v = csim[j]; int vi = cidx[j];
                if (v > best || (v == best && vi < bvix)) { best = v; bj = j; bvix = vi; }
            }
            used[bj] = true; sv5[k] = best; i5[k] = bvix;
        }
        float mx = sv5[0];
        float es[TOPK], sum = 0.0f;
        #pragma unroll
        for (int k = 0; k < TOPK; k++) { es[k] = expf((sv5[k] - mx) * TEMP); sum += es[k]; }
        #pragma unroll
        for (int k = 0; k < TOPK; k++) w5[k] = es[k] / sum;
    }
    __syncthreads();

    const float4* v0 = (const float4*)(voc + (size_t)i5[0] * DIM);
    const float4* v1 = (const float4*)(voc + (size_t)i5[1] * DIM);
    const float4* v2 = (const float4*)(voc + (size_t)i5[2] * DIM);
    const float4* v3 = (const float4*)(voc + (size_t)i5[3] * DIM);
    const float4* v4 = (const float4*)(voc + (size_t)i5[4] * DIM);
    float w0 = w5[0], w1 = w5[1], w2 = w5[2], w3 = w5[3], w4 = w5[4];
    float4* o4 = (float4*)(out + (size_t)row * DIM);

    for (int q = tid; q < DIM / 4; q += 256) {
        float4 e = s4[q];
        float4 a = v0[q], b = v1[q], c = v2[q], d = v3[q], f = v4[q];
        float4 r;
        r.x = ALPHA * e.x + (1.0f - ALPHA) * (w0 * a.x + w1 * b.x + w2 * c.x + w3 * d.x + w4 * f.x);
        r.y = ALPHA * e.y + (1.0f - ALPHA) * (w0 * a.y + w1 * b.y + w2 * c.y + w3 * d.y + w4 * f.y);
        r.z = ALPHA * e.z + (1.0f - ALPHA) * (w0 * a.z + w1 * b.z + w2 * c.z + w3 * d.z + w4 * f.z);
        r.w = ALPHA * e.w + (1.0f - ALPHA) * (w0 * a.w + w1 * b.w + w2 * c.w + w3 * d.w + w4 * f.w);
        o4[q] = r;
    }
}

// ---------------- launch -----------------------------------------------------
extern "C" void kernel_launch(void* const* d_in, const int* in_sizes, int n_in,
                              void* d_out, int out_size) {
    const float* emb = (const float*)d_in[0];
    const float* voc = (const float*)d_in[1];
    if (in_sizes[0] != NROWS * DIM) {   // defensive: identify by element count
        emb = (const float*)d_in[1];
        voc = (const float*)d_in[0];
    }
    float* out = (float*)d_out;

    prep_emb_kernel<<<NROWS, 256>>>(emb);
    prep_voc_kernel<<<VOCAB, 256>>>(voc);

    dim3 grid(NROWS / 128, VOCAB / 128);   // 64 x 250
    sim_gemm_kernel<<<grid, 256>>>();

    topm_kernel<<<NROWS, 256>>>();
    rescore_out_kernel<<<NROWS, 256>>>(emb, voc, out);
}

// round 4
// speedup vs baseline: 1.0968x; 1.0968x over previous
#include <cuda_runtime.h>
#include <cuda_bf16.h>
#include <mma.h>
#include <cstdint>

using namespace nvcuda;

#define NROWS 8192
#define DIM   2048
#define VOCAB 32000
#define TOPK  5
#define CAND  16
#define ALPHA 0.5f
#define TEMP  10.0f

// GEMM tiling
#define BM    128
#define BN    256
#define BKT   32
#define NKT   (DIM / BKT)          // 64 k-tiles
#define KPAD  40                   // padded row stride (elems) -> 80B, 16B-aligned
#define NSTG  3
#define STAGEA (BM * KPAD)         // elems
#define STAGEB (BN * KPAD)
#define STAGE_ELEMS (STAGEA + STAGEB)
#define GEMM_SMEM (NSTG * STAGE_ELEMS * 2)   // 92160 bytes

// ---------------- device scratch ----------------
__device__ __nv_bfloat16 g_embb[(size_t)NROWS * DIM];
__device__ __nv_bfloat16 g_vocb[(size_t)VOCAB * DIM];
__device__ __nv_bfloat16 g_sim [(size_t)NROWS * VOCAB];
__device__ float g_emb_inv[NROWS];
__device__ float g_voc_inv[VOCAB];
__device__ int   g_cand[NROWS * CAND];

// ---------------- helpers ----------------
__device__ __forceinline__ uint32_t smem_u32(const void* p) {
    uint32_t a;
    asm("{ .reg .u64 t; cvta.to.shared.u64 t, %1; cvt.u32.u64 %0, t; }" : "=r"(a) : "l"(p));
    return a;
}
#define CP16(dst_u32, src_ptr) \
    asm volatile("cp.async.cg.shared.global [%0], [%1], 16;" \
        :: "r"(dst_u32), "l"((unsigned long long)__cvta_generic_to_global((const void*)(src_ptr))) : "memory")
#define CP_COMMIT() asm volatile("cp.async.commit_group;" ::: "memory")
#define CP_WAIT(n)  asm volatile("cp.async.wait_group %0;" :: "n"(n) : "memory")

// ---------------- prep: norms + bf16 conversion -----------------------------
__global__ void __launch_bounds__(256) prep_emb_kernel(const float* __restrict__ emb) {
    int row = blockIdx.x;
    int t = threadIdx.x;
    const float4* s4 = (const float4*)(emb + (size_t)row * DIM);
    float4 a = s4[t * 2], b = s4[t * 2 + 1];
    float ss = a.x*a.x + a.y*a.y + a.z*a.z + a.w*a.w
             + b.x*b.x + b.y*b.y + b.z*b.z + b.w*b.w;
    __shared__ float red[256];
    red[t] = ss; __syncthreads();
    for (int o = 128; o > 0; o >>= 1) { if (t < o) red[t] += red[t + o]; __syncthreads(); }
    if (t == 0) g_emb_inv[row] = 1.0f / fmaxf(sqrtf(red[0]), 1e-12f);
    __nv_bfloat162* d2 = (__nv_bfloat162*)(g_embb + (size_t)row * DIM + t * 8);
    d2[0] = __floats2bfloat162_rn(a.x, a.y);
    d2[1] = __floats2bfloat162_rn(a.z, a.w);
    d2[2] = __floats2bfloat162_rn(b.x, b.y);
    d2[3] = __floats2bfloat162_rn(b.z, b.w);
}

__global__ void __launch_bounds__(256) prep_voc_kernel(const float* __restrict__ voc) {
    int row = blockIdx.x;
    int t = threadIdx.x;
    const float4* s4 = (const float4*)(voc + (size_t)row * DIM);
    float4 a = s4[t * 2], b = s4[t * 2 + 1];
    float ss = a.x*a.x + a.y*a.y + a.z*a.z + a.w*a.w
             + b.x*b.x + b.y*b.y + b.z*b.z + b.w*b.w;
    __shared__ float red[256];
    __shared__ float s_inv;
    red[t] = ss; __syncthreads();
    for (int o = 128; o > 0; o >>= 1) { if (t < o) red[t] += red[t + o]; __syncthreads(); }
    if (t == 0) {
        float inv = 1.0f / fmaxf(sqrtf(red[0]), 1e-12f);
        g_voc_inv[row] = inv;
        s_inv = inv;
    }
    __syncthreads();
    float inv = s_inv;
    __nv_bfloat162* d2 = (__nv_bfloat162*)(g_vocb + (size_t)row * DIM + t * 8);
    d2[0] = __floats2bfloat162_rn(a.x * inv, a.y * inv);
    d2[1] = __floats2bfloat162_rn(a.z * inv, a.w * inv);
    d2[2] = __floats2bfloat162_rn(b.x * inv, b.y * inv);
    d2[3] = __floats2bfloat162_rn(b.z * inv, b.w * inv);
}

// ---------------- GEMM: sim = embb @ vocb^T (cp.async 3-stage + wmma) -------
__device__ __forceinline__ void fill_stage(uint32_t as_u32, uint32_t bs_u32,
                                           int rowbase, int colbase, int kt, int tid) {
    // A: 128 rows x 2 chunks-of-16B-pairs -> 512 chunks, 2 per thread
    #pragma unroll
    for (int q = 0; q < 2; q++) {
        int c = tid + q * 256;
        int r = c >> 2, k16 = c & 3;
        uint32_t dst = as_u32 + (uint32_t)(r * KPAD + k16 * 8) * 2u;
        const __nv_bfloat16* src = g_embb + (size_t)(rowbase + r) * DIM + kt + k16 * 8;
        CP16(dst, src);
    }
    // B: 256 rows -> 1024 chunks, 4 per thread
    #pragma unroll
    for (int q = 0; q < 4; q++) {
        int c = tid + q * 256;
        int r = c >> 2, k16 = c & 3;
        uint32_t dst = bs_u32 + (uint32_t)(r * KPAD + k16 * 8) * 2u;
        const __nv_bfloat16* src = g_vocb + (size_t)(colbase + r) * DIM + kt + k16 * 8;
        CP16(dst, src);
    }
}

__global__ void __launch_bounds__(256, 1) sim_gemm_kernel() {
    extern __shared__ __align__(128) __nv_bfloat16 sm[];
    const int tid  = threadIdx.x;
    const int lane = tid & 31;
    const int wid  = tid >> 5;
    const int warp_m = wid >> 2;     // 0..1  -> 64-row band
    const int warp_n = wid & 3;      // 0..3  -> 64-col band
    const int rowbase = blockIdx.x * BM;
    const int colbase = blockIdx.y * BN;

    uint32_t s_u32[NSTG][2];
    #pragma unroll
    for (int s = 0; s < NSTG; s++) {
        s_u32[s][0] = smem_u32(sm + s * STAGE_ELEMS);
        s_u32[s][1] = smem_u32(sm + s * STAGE_ELEMS + STAGEA);
    }

    wmma::fragment<wmma::accumulator, 16, 16, 16, float> acc[4][4];
    #pragma unroll
    for (int i = 0; i < 4; i++)
        #pragma unroll
        for (int j = 0; j < 4; j++)
            wmma::fill_fragment(acc[i][j], 0.0f);

    // prologue: tiles 0 and 1
    fill_stage(s_u32[0][0], s_u32[0][1], rowbase, colbase, 0, tid);
    CP_COMMIT();
    fill_stage(s_u32[1][0], s_u32[1][1], rowbase, colbase, BKT, tid);
    CP_COMMIT();

    for (int i = 0; i < NKT; i++) {
        CP_WAIT(1);                 // tile i resident
        __syncthreads();            // all warps see it; stage (i-1)%3 reads done

        int j = i + 2;
        if (j < NKT) {
            int sj = j % NSTG;
            fill_stage(s_u32[sj][0], s_u32[sj][1], rowbase, colbase, j * BKT, tid);
        }
        CP_COMMIT();                // keep group accounting uniform

        const int s = i % NSTG;
        const __nv_bfloat16* As = sm + s * STAGE_ELEMS;
        const __nv_bfloat16* Bs = As + STAGEA;
        #pragma unroll
        for (int kk = 0; kk < 2; kk++) {
            wmma::fragment<wmma::matrix_a, 16, 16, 16, __nv_bfloat16, wmma::row_major> a[4];
            wmma::fragment<wmma::matrix_b, 16, 16, 16, __nv_bfloat16, wmma::col_major> b[4];
            #pragma unroll
            for (int x = 0; x < 4; x++)
                wmma::load_matrix_sync(a[x], As + (warp_m * 64 + x * 16) * KPAD + kk * 16, KPAD);
            #pragma unroll
            for (int y = 0; y < 4; y++)
                wmma::load_matrix_sync(b[y], Bs + (warp_n * 64 + y * 16) * KPAD + kk * 16, KPAD);
            #pragma unroll
            for (int x = 0; x < 4; x++)
                #pragma unroll
                for (int y = 0; y < 4; y++)
                    wmma::mma_sync(acc[x][y], a[x], b[y], acc[x][y]);
        }
    }

    __syncthreads();

    // epilogue: frag -> f32 smem (ldm=20) -> bf16x2 16B stores
    float* st = (float*)sm + wid * 320;     // 16 rows x 20
    const int er   = lane & 15;             // row in 16x16 block
    const int ehalf = lane >> 4;            // col half (0/1)
    #pragma unroll
    for (int x = 0; x < 4; x++) {
        #pragma unroll
        for (int y = 0; y < 4; y++) {
            wmma::store_matrix_sync(st, acc[x][y], 20, wmma::mem_row_major);
            __syncwarp();
            const float* srow = st + er * 20 + ehalf * 8;
            uint4 v;
            ((__nv_bfloat162*)&v)[0] = __floats2bfloat162_rn(srow[0], srow[1]);
            ((__nv_bfloat162*)&v)[1] = __floats2bfloat162_rn(srow[2], srow[3]);
            ((__nv_bfloat162*)&v)[2] = __floats2bfloat162_rn(srow[4], srow[5]);
            ((__nv_bfloat162*)&v)[3] = __floats2bfloat162_rn(srow[6], srow[7]);
            size_t gr = (size_t)(rowbase + warp_m * 64 + x * 16 + er);
            int    gc = colbase + warp_n * 64 + y * 16 + ehalf * 8;
            *(uint4*)(g_sim + gr * VOCAB + gc) = v;
            __syncwarp();
        }
    }
}

// ---------------- top-16 candidates per row ---------------------------------
__global__ void __launch_bounds__(256) topm_kernel() {
    int row = blockIdx.x;
    int tid = threadIdx.x;
    const __nv_bfloat162* s2 = (const __nv_bfloat162*)(g_sim + (size_t)row * VOCAB);

    float lv[CAND];
    int   li[CAND];
    #pragma unroll
    for (int i = 0; i < CAND; i++) { lv[i] = -1e30f; li[i] = -1; }

    for (int j = tid; j < VOCAB / 2; j += 256) {
        __nv_bfloat162 pv = s2[j];
        float v0 = __bfloat162float(pv.x);
        float v1 = __bfloat162float(pv.y);
        if (v0 > lv[CAND - 1]) {
            int p = CAND - 1;
            while (p > 0 && lv[p - 1] < v0) { lv[p] = lv[p - 1]; li[p] = li[p - 1]; p--; }
            lv[p] = v0; li[p] = 2 * j;
        }
        if (v1 > lv[CAND - 1]) {
            int p = CAND - 1;
            while (p > 0 && lv[p - 1] < v1) { lv[p] = lv[p - 1]; li[p] = li[p - 1]; p--; }
            lv[p] = v1; li[p] = 2 * j + 1;
        }
    }

    __shared__ float sv[256 * CAND];
    __shared__ int   si[256 * CAND];
    #pragma unroll
    for (int i = 0; i < CAND; i++) { sv[tid * CAND + i] = lv[i]; si[tid * CAND + i] = li[i]; }
    __syncthreads();

    __shared__ float bv[256];
    __shared__ int   bvi[256];
    __shared__ int   bo[256];
    for (int k = 0; k < CAND; k++) {
        float best = -1e30f; int bi = 0x7fffffff; int bofs = 0;
        for (int e = tid; e < 256 * CAND; e += 256) {
            float v = sv[e]; int ii = si[e];
            if (v > best || (v == best && ii >= 0 && ii < bi)) { best = v; bi = ii; bofs = e; }
        }
        bv[tid] = best; bvi[tid] = bi; bo[tid] = bofs;
        __syncthreads();
        for (int o = 128; o > 0; o >>= 1) {
            if (tid < o) {
                if (bv[tid + o] > bv[tid] ||
                    (bv[tid + o] == bv[tid] && bvi[tid + o] < bvi[tid])) {
                    bv[tid] = bv[tid + o]; bvi[tid] = bvi[tid + o]; bo[tid] = bo[tid + o];
                }
            }
            __syncthreads();
        }
        if (tid == 0) {
            g_cand[row * CAND + k] = bvi[0];
            sv[bo[0]] = -1e30f;
        }
        __syncthreads();
    }
}

// ---------------- exact fp32 rescore + softmax + projection -----------------
__global__ void __launch_bounds__(256) rescore_out_kernel(
    const float* __restrict__ emb, const float* __restrict__ voc,
    float* __restrict__ out)
{
    int row  = blockIdx.x;
    int tid  = threadIdx.x;
    int lane = tid & 31;
    int wid  = tid >> 5;

    __shared__ float semb[DIM];
    const float4* e4 = (const float4*)(emb + (size_t)row * DIM);
    float4* s4 = (float4*)semb;
    for (int q = tid; q < DIM / 4; q += 256) s4[q] = e4[q];

    __shared__ int   cidx[CAND];
    __shared__ float csim[CAND];
    if (tid < CAND) cidx[tid] = g_cand[row * CAND + tid];
    __syncthreads();

    float inv_e = g_emb_inv[row];
    #pragma unroll
    for (int s = 0; s < 2; s++) {
        int c = wid * 2 + s;
        int v = cidx[c];
        const float4* vr = (const float4*)(voc + (size_t)v * DIM);
        float acc = 0.0f;
        for (int d = lane; d < DIM / 4; d += 32) {
            float4 a = s4[d];
            float4 b = vr[d];
            acc += a.x * b.x + a.y * b.y + a.z * b.z + a.w * b.w;
        }
        #pragma unroll
        for (int o = 16; o > 0; o >>= 1) acc += __shfl_xor_sync(0xffffffffu, acc, o);
        if (lane == 0) csim[c] = acc * inv_e * g_voc_inv[v];
    }
    __syncthreads();

    __shared__ float w5[TOPK];
    __shared__ int   i5[TOPK];
    if (tid == 0) {
        bool used[CAND];
        #pragma unroll
        for (int j = 0; j < CAND; j++) used[j] = false;
        float sv5[TOPK];
        for (int k = 0; k < TOPK; k++) {
            float best = -1e30f; int bj = -1; int bvix = 0x7fffffff;
            for (int j = 0; j < CAND; j++) {
                if (used[j]) continue;
                float v = csim[j]; int vi = cidx[j];
                if (v > best || (v == best && vi < bvix)) { best = v; bj = j; bvix = vi; }
            }
            used[bj] = true; sv5[k] = best; i5[k] = bvix;
        }
        float mx = sv5[0];
        float es[TOPK], sum = 0.0f;
        #pragma unroll
        for (int k = 0; k < TOPK; k++) { es[k] = expf((sv5[k] - mx) * TEMP); sum += es[k]; }
        #pragma unroll
        for (int k = 0; k < TOPK; k++) w5[k] = es[k] / sum;
    }
    __syncthreads();

    const float4* v0 = (const float4*)(voc + (size_t)i5[0] * DIM);
    const float4* v1 = (const float4*)(voc + (size_t)i5[1] * DIM);
    const float4* v2 = (const float4*)(voc + (size_t)i5[2] * DIM);
    const float4* v3 = (const float4*)(voc + (size_t)i5[3] * DIM);
    const float4* v4 = (const float4*)(voc + (size_t)i5[4] * DIM);
    float w0 = w5[0], w1 = w5[1], w2 = w5[2], w3 = w5[3], w4 = w5[4];
    float4* o4 = (float4*)(out + (size_t)row * DIM);

    for (int q = tid; q < DIM / 4; q += 256) {
        float4 e = s4[q];
        float4 a = v0[q], b = v1[q], c = v2[q], d = v3[q], f = v4[q];
        float4 r;
        r.x = ALPHA * e.x + (1.0f - ALPHA) * (w0 * a.x + w1 * b.x + w2 * c.x + w3 * d.x + w4 * f.x);
        r.y = ALPHA * e.y + (1.0f - ALPHA) * (w0 * a.y + w1 * b.y + w2 * c.y + w3 * d.y + w4 * f.y);
        r.z = ALPHA * e.z + (1.0f - ALPHA) * (w0 * a.z + w1 * b.z + w2 * c.z + w3 * d.z + w4 * f.z);
        r.w = ALPHA * e.w + (1.0f - ALPHA) * (w0 * a.w + w1 * b.w + w2 * c.w + w3 * d.w + w4 * f.w);
        o4[q] = r;
    }
}

// ---------------- launch -----------------------------------------------------
extern "C" void kernel_launch(void* const* d_in, const int* in_sizes, int n_in,
                              void* d_out, int out_size) {
    const float* emb = (const float*)d_in[0];
    const float* voc = (const float*)d_in[1];
    if (in_sizes[0] != NROWS * DIM) {
        emb = (const float*)d_in[1];
        voc = (const float*)d_in[0];
    }
    float* out = (float*)d_out;

    prep_emb_kernel<<<NROWS, 256>>>(emb);
    prep_voc_kernel<<<VOCAB, 256>>>(voc);

    cudaFuncSetAttribute(sim_gemm_kernel,
                         cudaFuncAttributeMaxDynamicSharedMemorySize, GEMM_SMEM);
    dim3 grid(NROWS / BM, VOCAB / BN);   // 64 x 125
    sim_gemm_kernel<<<grid, 256, GEMM_SMEM>>>();

    topm_kernel<<<NROWS, 256>>>();
    rescore_out_kernel<<<NROWS, 256>>>(emb, voc, out);
}

// round 5
// speedup vs baseline: 1.3058x; 1.1905x over previous
#include <cuda_runtime.h>
#include <cuda_bf16.h>
#include <cstdint>

#define NROWS 8192
#define DIM   2048
#define VOCAB 32000
#define TOPK  5
#define CAND  16
#define ALPHA 0.5f
#define TEMP  10.0f

// GEMM tiling
#define BM    128
#define BN    256
#define BK    64                    // k elems per tile (128 bytes)
#define NKT   (DIM / BK)            // 32
#define NSTG  4
#define A_BYTES (BM * 128)          // 16 KB
#define B_BYTES (BN * 128)          // 32 KB
#define STG_BYTES (A_BYTES + B_BYTES)
#define GEMM_SMEM (NSTG * STG_BYTES)   // 192 KB

// ---------------- device scratch ----------------
__device__ __nv_bfloat16 g_embb[(size_t)NROWS * DIM];
__device__ __nv_bfloat16 g_vocb[(size_t)VOCAB * DIM];
__device__ __nv_bfloat16 g_sim [(size_t)NROWS * VOCAB];
__device__ float g_emb_inv[NROWS];
__device__ float g_voc_inv[VOCAB];
__device__ int   g_cand[NROWS * CAND];

// ---------------- helpers ----------------
__device__ __forceinline__ uint32_t smem_u32(const void* p) {
    uint32_t a;
    asm("{ .reg .u64 t; cvta.to.shared.u64 t, %1; cvt.u32.u64 %0, t; }" : "=r"(a) : "l"(p));
    return a;
}
#define CP16(dst_u32, src_ptr) \
    asm volatile("cp.async.cg.shared.global [%0], [%1], 16;" \
        :: "r"(dst_u32), "l"((unsigned long long)__cvta_generic_to_global((const void*)(src_ptr))) : "memory")
#define CP_COMMIT() asm volatile("cp.async.commit_group;" ::: "memory")
#define CP_WAIT(n)  asm volatile("cp.async.wait_group %0;" :: "n"(n) : "memory")

__device__ __forceinline__ void ldsm4(uint32_t& d0, uint32_t& d1, uint32_t& d2, uint32_t& d3,
                                      uint32_t addr) {
    asm volatile("ldmatrix.sync.aligned.m8n8.x4.shared.b16 {%0,%1,%2,%3}, [%4];"
                 : "=r"(d0), "=r"(d1), "=r"(d2), "=r"(d3) : "r"(addr));
}
#define MMA16816(d, a, b) \
    asm volatile("mma.sync.aligned.m16n8k16.row.col.f32.bf16.bf16.f32 " \
        "{%0,%1,%2,%3}, {%4,%5,%6,%7}, {%8,%9}, {%0,%1,%2,%3};" \
        : "+f"((d)[0]), "+f"((d)[1]), "+f"((d)[2]), "+f"((d)[3]) \
        : "r"((a)[0]), "r"((a)[1]), "r"((a)[2]), "r"((a)[3]), "r"((b)[0]), "r"((b)[1]))

// ---------------- prep: norms + bf16 conversion -----------------------------
__global__ void __launch_bounds__(256) prep_emb_kernel(const float* __restrict__ emb) {
    int row = blockIdx.x;
    int t = threadIdx.x;
    const float4* s4 = (const float4*)(emb + (size_t)row * DIM);
    float4 a = s4[t * 2], b = s4[t * 2 + 1];
    float ss = a.x*a.x + a.y*a.y + a.z*a.z + a.w*a.w
             + b.x*b.x + b.y*b.y + b.z*b.z + b.w*b.w;
    __shared__ float red[256];
    red[t] = ss; __syncthreads();
    for (int o = 128; o > 0; o >>= 1) { if (t < o) red[t] += red[t + o]; __syncthreads(); }
    if (t == 0) g_emb_inv[row] = 1.0f / fmaxf(sqrtf(red[0]), 1e-12f);
    __nv_bfloat162* d2 = (__nv_bfloat162*)(g_embb + (size_t)row * DIM + t * 8);
    d2[0] = __floats2bfloat162_rn(a.x, a.y);
    d2[1] = __floats2bfloat162_rn(a.z, a.w);
    d2[2] = __floats2bfloat162_rn(b.x, b.y);
    d2[3] = __floats2bfloat162_rn(b.z, b.w);
}

__global__ void __launch_bounds__(256) prep_voc_kernel(const float* __restrict__ voc) {
    int row = blockIdx.x;
    int t = threadIdx.x;
    const float4* s4 = (const float4*)(voc + (size_t)row * DIM);
    float4 a = s4[t * 2], b = s4[t * 2 + 1];
    float ss = a.x*a.x + a.y*a.y + a.z*a.z + a.w*a.w
             + b.x*b.x + b.y*b.y + b.z*b.z + b.w*b.w;
    __shared__ float red[256];
    __shared__ float s_inv;
    red[t] = ss; __syncthreads();
    for (int o = 128; o > 0; o >>= 1) { if (t < o) red[t] += red[t + o]; __syncthreads(); }
    if (t == 0) {
        float inv = 1.0f / fmaxf(sqrtf(red[0]), 1e-12f);
        g_voc_inv[row] = inv;
        s_inv = inv;
    }
    __syncthreads();
    float inv = s_inv;
    __nv_bfloat162* d2 = (__nv_bfloat162*)(g_vocb + (size_t)row * DIM + t * 8);
    d2[0] = __floats2bfloat162_rn(a.x * inv, a.y * inv);
    d2[1] = __floats2bfloat162_rn(a.z * inv, a.w * inv);
    d2[2] = __floats2bfloat162_rn(b.x * inv, b.y * inv);
    d2[3] = __floats2bfloat162_rn(b.z * inv, b.w * inv);
}

// ---------------- GEMM: sim = embb @ vocb^T ---------------------------------
// 128x256 CTA tile, BK=64, 8 warps (2m x 4n), warp tile 64x64.
// smem: per stage A[128][128B] + B[256][128B], XOR-swizzled 16B chunks.
__device__ __forceinline__ void fill_stage(uint32_t a_u32, uint32_t b_u32,
                                           int rowbase, int colbase, int kt, int tid) {
    #pragma unroll
    for (int q = 0; q < 4; q++) {                // A: 1024 chunks
        int idx = tid + q * 256;
        int r = idx >> 3, c = idx & 7;
        uint32_t dst = a_u32 + (uint32_t)(r * 128 + ((c ^ (r & 7)) << 4));
        CP16(dst, g_embb + (size_t)(rowbase + r) * DIM + kt + c * 8);
    }
    #pragma unroll
    for (int q = 0; q < 8; q++) {                // B: 2048 chunks
        int idx = tid + q * 256;
        int r = idx >> 3, c = idx & 7;
        uint32_t dst = b_u32 + (uint32_t)(r * 128 + ((c ^ (r & 7)) << 4));
        CP16(dst, g_vocb + (size_t)(colbase + r) * DIM + kt + c * 8);
    }
}

__global__ void __launch_bounds__(256, 1) sim_gemm_kernel() {
    extern __shared__ __align__(128) char sm[];
    const uint32_t sbase = smem_u32(sm);
    const int tid  = threadIdx.x;
    const int lane = tid & 31;
    const int wid  = tid >> 5;
    const int warp_m = wid >> 2;          // 0..1 -> 64-row band
    const int warp_n = wid & 3;           // 0..3 -> 64-col band
    const int rowbase = blockIdx.x * BM;
    const int colbase = blockIdx.y * BN;

    // ldmatrix addressing (per-thread constants)
    const int a_r  = lane & 15;
    const int a_c  = lane >> 4;           // 0/1 = k-chunk select
    const int a_x7 = a_r & 7;
    uint32_t a_off[4];
    #pragma unroll
    for (int x = 0; x < 4; x++)
        a_off[x] = (uint32_t)((warp_m * 64 + x * 16 + a_r) * 128);

    const int b_q  = lane >> 3;           // 0..3
    const int b_nl = ((b_q >> 1) << 3) | (lane & 7);
    const int b_c  = b_q & 1;
    const int b_x7 = lane & 7;
    uint32_t b_off[4];
    #pragma unroll
    for (int jp = 0; jp < 4; jp++)
        b_off[jp] = (uint32_t)((warp_n * 64 + jp * 16 + b_nl) * 128);

    float acc[4][8][4];
    #pragma unroll
    for (int x = 0; x < 4; x++)
        #pragma unroll
        for (int j = 0; j < 8; j++)
            #pragma unroll
            for (int r = 0; r < 4; r++)
                acc[x][j][r] = 0.0f;

    // prologue: tiles 0..2
    #pragma unroll
    for (int p = 0; p < NSTG - 1; p++) {
        uint32_t ab = sbase + p * STG_BYTES;
        fill_stage(ab, ab + A_BYTES, rowbase, colbase, p * BK, tid);
        CP_COMMIT();
    }

    for (int i = 0; i < NKT; i++) {
        CP_WAIT(NSTG - 2);          // tile i resident
        __syncthreads();

        int j = i + NSTG - 1;
        if (j < NKT) {
            uint32_t ab = sbase + (j % NSTG) * STG_BYTES;
            fill_stage(ab, ab + A_BYTES, rowbase, colbase, j * BK, tid);
        }
        CP_COMMIT();

        const uint32_t aB = sbase + (i % NSTG) * STG_BYTES;
        const uint32_t bB = aB + A_BYTES;
        #pragma unroll
        for (int s = 0; s < 4; s++) {
            uint32_t af[4][4];
            #pragma unroll
            for (int x = 0; x < 4; x++)
                ldsm4(af[x][0], af[x][1], af[x][2], af[x][3],
                      aB + a_off[x] + (uint32_t)(((((s << 1) | a_c)) ^ a_x7) << 4));
            uint32_t bf[8][2];
            #pragma unroll
            for (int jp = 0; jp < 4; jp++)
                ldsm4(bf[2*jp][0], bf[2*jp][1], bf[2*jp+1][0], bf[2*jp+1][1],
                      bB + b_off[jp] + (uint32_t)(((((s << 1) | b_c)) ^ b_x7) << 4));
            #pragma unroll
            for (int x = 0; x < 4; x++)
                #pragma unroll
                for (int j2 = 0; j2 < 8; j2++)
                    MMA16816(acc[x][j2], af[x], bf[j2]);
        }
    }

    // epilogue: direct bf16x2 stores (acc thread map: row=t/4(+8), col=2*(t%4)+{0,1})
    const int tr = lane >> 2;
    const int tc = (lane & 3) * 2;
    #pragma unroll
    for (int x = 0; x < 4; x++) {
        size_t row0 = (size_t)(rowbase + warp_m * 64 + x * 16 + tr);
        #pragma unroll
        for (int j2 = 0; j2 < 8; j2++) {
            int col = colbase + warp_n * 64 + j2 * 8 + tc;
            *(__nv_bfloat162*)(g_sim + row0 * VOCAB + col) =
                __floats2bfloat162_rn(acc[x][j2][0], acc[x][j2][1]);
            *(__nv_bfloat162*)(g_sim + (row0 + 8) * VOCAB + col) =
                __floats2bfloat162_rn(acc[x][j2][2], acc[x][j2][3]);
        }
    }
}

// ---------------- top-16 candidates per row ---------------------------------
__global__ void __launch_bounds__(256) topm_kernel() {
    int row = blockIdx.x;
    int tid = threadIdx.x;
    const __nv_bfloat162* s2 = (const __nv_bfloat162*)(g_sim + (size_t)row * VOCAB);

    float lv[CAND];
    int   li[CAND];
    #pragma unroll
    for (int i = 0; i < CAND; i++) { lv[i] = -1e30f; li[i] = -1; }

    for (int j = tid; j < VOCAB / 2; j += 256) {
        __nv_bfloat162 pv = s2[j];
        float v0 = __bfloat162float(pv.x);
        float v1 = __bfloat162float(pv.y);
        if (v0 > lv[CAND - 1]) {
            int p = CAND - 1;
            while (p > 0 && lv[p - 1] < v0) { lv[p] = lv[p - 1]; li[p] = li[p - 1]; p--; }
            lv[p] = v0; li[p] = 2 * j;
        }
        if (v1 > lv[CAND - 1]) {
            int p = CAND - 1;
            while (p > 0 && lv[p - 1] < v1) { lv[p] = lv[p - 1]; li[p] = li[p - 1]; p--; }
            lv[p] = v1; li[p] = 2 * j + 1;
        }
    }

    __shared__ float sv[256 * CAND];
    __shared__ int   si[256 * CAND];
    #pragma unroll
    for (int i = 0; i < CAND; i++) { sv[tid * CAND + i] = lv[i]; si[tid * CAND + i] = li[i]; }
    __syncthreads();

    __shared__ float bv[256];
    __shared__ int   bvi[256];
    __shared__ int   bo[256];
    for (int k = 0; k < CAND; k++) {
        float best = -1e30f; int bi = 0x7fffffff; int bofs = 0;
        for (int e = tid; e < 256 * CAND; e += 256) {
            float v = sv[e]; int ii = si[e];
            if (v > best || (v == best && ii >= 0 && ii < bi)) { best = v; bi = ii; bofs = e; }
        }
        bv[tid] = best; bvi[tid] = bi; bo[tid] = bofs;
        __syncthreads();
        for (int o = 128; o > 0; o >>= 1) {
            if (tid < o) {
                if (bv[tid + o] > bv[tid] ||
                    (bv[tid + o] == bv[tid] && bvi[tid + o] < bvi[tid])) {
                    bv[tid] = bv[tid + o]; bvi[tid] = bvi[tid + o]; bo[tid] = bo[tid + o];
                }
            }
            __syncthreads();
        }
        if (tid == 0) {
            g_cand[row * CAND + k] = bvi[0];
            sv[bo[0]] = -1e30f;
        }
        __syncthreads();
    }
}

// ---------------- exact fp32 rescore + softmax + projection -----------------
__global__ void __launch_bounds__(256) rescore_out_kernel(
    const float* __restrict__ emb, const float* __restrict__ voc,
    float* __restrict__ out)
{
    int row  = blockIdx.x;
    int tid  = threadIdx.x;
    int lane = tid & 31;
    int wid  = tid >> 5;

    __shared__ float semb[DIM];
    const float4* e4 = (const float4*)(emb + (size_t)row * DIM);
    float4* s4 = (float4*)semb;
    for (int q = tid; q < DIM / 4; q += 256) s4[q] = e4[q];

    __shared__ int   cidx[CAND];
    __shared__ float csim[CAND];
    if (tid < CAND) cidx[tid] = g_cand[row * CAND + tid];
    __syncthreads();

    float inv_e = g_emb_inv[row];
    #pragma unroll
    for (int s = 0; s < 2; s++) {
        int c = wid * 2 + s;
        int v = cidx[c];
        const float4* vr = (const float4*)(voc + (size_t)v * DIM);
        float acc = 0.0f;
        for (int d = lane; d < DIM / 4; d += 32) {
            float4 a = s4[d];
            float4 b = vr[d];
            acc += a.x * b.x + a.y * b.y + a.z * b.z + a.w * b.w;
        }
        #pragma unroll
        for (int o = 16; o > 0; o >>= 1) acc += __shfl_xor_sync(0xffffffffu, acc, o);
        if (lane == 0) csim[c] = acc * inv_e * g_voc_inv[v];
    }
    __syncthreads();

    __shared__ float w5[TOPK];
    __shared__ int   i5[TOPK];
    if (tid == 0) {
        bool used[CAND];
        #pragma unroll
        for (int j = 0; j < CAND; j++) used[j] = false;
        float sv5[TOPK];
        for (int k = 0; k < TOPK; k++) {
            float best = -1e30f; int bj = -1; int bvix = 0x7fffffff;
            for (int j = 0; j < CAND; j++) {
                if (used[j]) continue;
                float v = csim[j]; int vi = cidx[j];
                if (v > best || (v == best && vi < bvix)) { best = v; bj = j; bvix = vi; }
            }
            used[bj] = true; sv5[k] = best; i5[k] = bvix;
        }
        float mx = sv5[0];
        float es[TOPK], sum = 0.0f;
        #pragma unroll
        for (int k = 0; k < TOPK; k++) { es[k] = expf((sv5[k] - mx) * TEMP); sum += es[k]; }
        #pragma unroll
        for (int k = 0; k < TOPK; k++) w5[k] = es[k] / sum;
    }
    __syncthreads();

    const float4* v0 = (const float4*)(voc + (size_t)i5[0] * DIM);
    const float4* v1 = (const float4*)(voc + (size_t)i5[1] * DIM);
    const float4* v2 = (const float4*)(voc + (size_t)i5[2] * DIM);
    const float4* v3 = (const float4*)(voc + (size_t)i5[3] * DIM);
    const float4* v4 = (const float4*)(voc + (size_t)i5[4] * DIM);
    float w0 = w5[0], w1 = w5[1], w2 = w5[2], w3 = w5[3], w4 = w5[4];
    float4* o4 = (float4*)(out + (size_t)row * DIM);

    for (int q = tid; q < DIM / 4; q += 256) {
        float4 e = s4[q];
        float4 a = v0[q], b = v1[q], c = v2[q], d = v3[q], f = v4[q];
        float4 r;
        r.x = ALPHA * e.x + (1.0f - ALPHA) * (w0 * a.x + w1 * b.x + w2 * c.x + w3 * d.x + w4 * f.x);
        r.y = ALPHA * e.y + (1.0f - ALPHA) * (w0 * a.y + w1 * b.y + w2 * c.y + w3 * d.y + w4 * f.y);
        r.z = ALPHA * e.z + (1.0f - ALPHA) * (w0 * a.z + w1 * b.z + w2 * c.z + w3 * d.z + w4 * f.z);
        r.w = ALPHA * e.w + (1.0f - ALPHA) * (w0 * a.w + w1 * b.w + w2 * c.w + w3 * d.w + w4 * f.w);
        o4[q] = r;
    }
}

// ---------------- launch -----------------------------------------------------
extern "C" void kernel_launch(void* const* d_in, const int* in_sizes, int n_in,
                              void* d_out, int out_size) {
    const float* emb = (const float*)d_in[0];
    const float* voc = (const float*)d_in[1];
    if (in_sizes[0] != NROWS * DIM) {
        emb = (const float*)d_in[1];
        voc = (const float*)d_in[0];
    }
    float* out = (float*)d_out;

    prep_emb_kernel<<<NROWS, 256>>>(emb);
    prep_voc_kernel<<<VOCAB, 256>>>(voc);

    cudaFuncSetAttribute(sim_gemm_kernel,
                         cudaFuncAttributeMaxDynamicSharedMemorySize, GEMM_SMEM);
    dim3 grid(NROWS / BM, VOCAB / BN);   // 64 x 125, rows-fastest for B reuse in L2
    sim_gemm_kernel<<<grid, 256, GEMM_SMEM>>>();

    topm_kernel<<<NROWS, 256>>>();
    rescore_out_kernel<<<NROWS, 256>>>(emb, voc, out);
}

// round 6
// speedup vs baseline: 1.4699x; 1.1257x over previous
#include <cuda_runtime.h>
#include <cuda_bf16.h>
#include <cstdint>

#define NROWS 8192
#define DIM   2048
#define VOCAB 32000
#define TOPK  5
#define CAND  32
#define LOCK  8                     // per-thread local top-k in screen
#define ALPHA 0.5f
#define TEMP  10.0f
#define QSCALE 976.0f               // int8 quant scale for normalized vectors

// GEMM tiling (int8): CTA 128x256, k-tile 128 int8 (=128B rows)
#define BM    128
#define BN    256
#define BKB   128                   // k bytes per tile
#define NKT   (DIM / BKB)           // 16
#define NSTG  4
#define A_BYTES (BM * 128)          // 16 KB
#define B_BYTES (BN * 128)          // 32 KB
#define STG_BYTES (A_BYTES + B_BYTES)
#define GEMM_SMEM (NSTG * STG_BYTES)   // 192 KB

// ---------------- device scratch ----------------
__device__ int8_t g_embq[(size_t)NROWS * DIM];
__device__ int8_t g_vocq[(size_t)VOCAB * DIM];
__device__ int    g_simi[(size_t)NROWS * VOCAB];     // exact s32 screen sims
__device__ float  g_emb_inv[NROWS];
__device__ float  g_voc_inv[VOCAB];
__device__ int    g_cand[NROWS * CAND];

// ---------------- helpers ----------------
__device__ __forceinline__ uint32_t smem_u32(const void* p) {
    uint32_t a;
    asm("{ .reg .u64 t; cvta.to.shared.u64 t, %1; cvt.u32.u64 %0, t; }" : "=r"(a) : "l"(p));
    return a;
}
#define CP16(dst_u32, src_ptr) \
    asm volatile("cp.async.cg.shared.global [%0], [%1], 16;" \
        :: "r"(dst_u32), "l"((unsigned long long)__cvta_generic_to_global((const void*)(src_ptr))) : "memory")
#define CP_COMMIT() asm volatile("cp.async.commit_group;" ::: "memory")
#define CP_WAIT(n)  asm volatile("cp.async.wait_group %0;" :: "n"(n) : "memory")

__device__ __forceinline__ void ldsm4(uint32_t& d0, uint32_t& d1, uint32_t& d2, uint32_t& d3,
                                      uint32_t addr) {
    asm volatile("ldmatrix.sync.aligned.m8n8.x4.shared.b16 {%0,%1,%2,%3}, [%4];"
                 : "=r"(d0), "=r"(d1), "=r"(d2), "=r"(d3) : "r"(addr));
}
#define MMA16832S8(d, a, b) \
    asm volatile("mma.sync.aligned.m16n8k32.row.col.s32.s8.s8.s32 " \
        "{%0,%1,%2,%3}, {%4,%5,%6,%7}, {%8,%9}, {%0,%1,%2,%3};" \
        : "+r"((d)[0]), "+r"((d)[1]), "+r"((d)[2]), "+r"((d)[3]) \
        : "r"((a)[0]), "r"((a)[1]), "r"((a)[2]), "r"((a)[3]), "r"((b)[0]), "r"((b)[1]))

__device__ __forceinline__ int8_t quant(float x) {
    int v = __float2int_rn(x * QSCALE);
    v = max(-127, min(127, v));
    return (int8_t)v;
}

// ---------------- prep: norms + int8 quantized normalized vectors -----------
__global__ void __launch_bounds__(256) prep_emb_kernel(const float* __restrict__ emb) {
    int row = blockIdx.x;
    int t = threadIdx.x;
    const float4* s4 = (const float4*)(emb + (size_t)row * DIM);
    float4 a = s4[t * 2], b = s4[t * 2 + 1];
    float ss = a.x*a.x + a.y*a.y + a.z*a.z + a.w*a.w
             + b.x*b.x + b.y*b.y + b.z*b.z + b.w*b.w;
    __shared__ float red[256];
    __shared__ float s_inv;
    red[t] = ss; __syncthreads();
    for (int o = 128; o > 0; o >>= 1) { if (t < o) red[t] += red[t + o]; __syncthreads(); }
    if (t == 0) {
        float inv = 1.0f / fmaxf(sqrtf(red[0]), 1e-12f);
        g_emb_inv[row] = inv;
        s_inv = inv;
    }
    __syncthreads();
    float inv = s_inv;
    uint8_t q[8];
    q[0]=(uint8_t)quant(a.x*inv); q[1]=(uint8_t)quant(a.y*inv);
    q[2]=(uint8_t)quant(a.z*inv); q[3]=(uint8_t)quant(a.w*inv);
    q[4]=(uint8_t)quant(b.x*inv); q[5]=(uint8_t)quant(b.y*inv);
    q[6]=(uint8_t)quant(b.z*inv); q[7]=(uint8_t)quant(b.w*inv);
    uint2 pk;
    pk.x = (uint32_t)q[0] | ((uint32_t)q[1]<<8) | ((uint32_t)q[2]<<16) | ((uint32_t)q[3]<<24);
    pk.y = (uint32_t)q[4] | ((uint32_t)q[5]<<8) | ((uint32_t)q[6]<<16) | ((uint32_t)q[7]<<24);
    *(uint2*)(g_embq + (size_t)row * DIM + t * 8) = pk;
}

__global__ void __launch_bounds__(256) prep_voc_kernel(const float* __restrict__ voc) {
    int row = blockIdx.x;
    int t = threadIdx.x;
    const float4* s4 = (const float4*)(voc + (size_t)row * DIM);
    float4 a = s4[t * 2], b = s4[t * 2 + 1];
    float ss = a.x*a.x + a.y*a.y + a.z*a.z + a.w*a.w
             + b.x*b.x + b.y*b.y + b.z*b.z + b.w*b.w;
    __shared__ float red[256];
    __shared__ float s_inv;
    red[t] = ss; __syncthreads();
    for (int o = 128; o > 0; o >>= 1) { if (t < o) red[t] += red[t + o]; __syncthreads(); }
    if (t == 0) {
        float inv = 1.0f / fmaxf(sqrtf(red[0]), 1e-12f);
        g_voc_inv[row] = inv;
        s_inv = inv;
    }
    __syncthreads();
    float inv = s_inv;
    uint8_t q[8];
    q[0]=(uint8_t)quant(a.x*inv); q[1]=(uint8_t)quant(a.y*inv);
    q[2]=(uint8_t)quant(a.z*inv); q[3]=(uint8_t)quant(a.w*inv);
    q[4]=(uint8_t)quant(b.x*inv); q[5]=(uint8_t)quant(b.y*inv);
    q[6]=(uint8_t)quant(b.z*inv); q[7]=(uint8_t)quant(b.w*inv);
    uint2 pk;
    pk.x = (uint32_t)q[0] | ((uint32_t)q[1]<<8) | ((uint32_t)q[2]<<16) | ((uint32_t)q[3]<<24);
    pk.y = (uint32_t)q[4] | ((uint32_t)q[5]<<8) | ((uint32_t)q[6]<<16) | ((uint32_t)q[7]<<24);
    *(uint2*)(g_vocq + (size_t)row * DIM + t * 8) = pk;
}

// ---------------- int8 screen GEMM: g_simi = embq @ vocq^T ------------------
__device__ __forceinline__ void fill_stage(uint32_t a_u32, uint32_t b_u32,
                                           int rowbase, int colbase, int ktB, int tid) {
    #pragma unroll
    for (int q = 0; q < 4; q++) {                // A: 1024 x 16B chunks
        int idx = tid + q * 256;
        int r = idx >> 3, c = idx & 7;
        uint32_t dst = a_u32 + (uint32_t)(r * 128 + ((c ^ (r & 7)) << 4));
        CP16(dst, g_embq + (size_t)(rowbase + r) * DIM + ktB + c * 16);
    }
    #pragma unroll
    for (int q = 0; q < 8; q++) {                // B: 2048 x 16B chunks
        int idx = tid + q * 256;
        int r = idx >> 3, c = idx & 7;
        uint32_t dst = b_u32 + (uint32_t)(r * 128 + ((c ^ (r & 7)) << 4));
        CP16(dst, g_vocq + (size_t)(colbase + r) * DIM + ktB + c * 16);
    }
}

__global__ void __launch_bounds__(256, 1) sim_gemm_kernel() {
    extern __shared__ __align__(128) char sm[];
    const uint32_t sbase = smem_u32(sm);
    const int tid  = threadIdx.x;
    const int lane = tid & 31;
    const int wid  = tid >> 5;
    const int warp_m = wid >> 2;
    const int warp_n = wid & 3;
    const int rowbase = blockIdx.x * BM;
    const int colbase = blockIdx.y * BN;

    // ldmatrix addressing (byte-identical to bf16 case; 128B k-rows)
    const int a_r  = lane & 15;
    const int a_c  = lane >> 4;
    const int a_x7 = a_r & 7;
    uint32_t a_off[4];
    #pragma unroll
    for (int x = 0; x < 4; x++)
        a_off[x] = (uint32_t)((warp_m * 64 + x * 16 + a_r) * 128);

    const int b_q  = lane >> 3;
    const int b_nl = ((b_q >> 1) << 3) | (lane & 7);
    const int b_c  = b_q & 1;
    const int b_x7 = lane & 7;
    uint32_t b_off[4];
    #pragma unroll
    for (int jp = 0; jp < 4; jp++)
        b_off[jp] = (uint32_t)((warp_n * 64 + jp * 16 + b_nl) * 128);

    int acc[4][8][4];
    #pragma unroll
    for (int x = 0; x < 4; x++)
        #pragma unroll
        for (int j = 0; j < 8; j++)
            #pragma unroll
            for (int r = 0; r < 4; r++)
                acc[x][j][r] = 0;

    #pragma unroll
    for (int p = 0; p < NSTG - 1; p++) {
        uint32_t ab = sbase + p * STG_BYTES;
        fill_stage(ab, ab + A_BYTES, rowbase, colbase, p * BKB, tid);
        CP_COMMIT();
    }

    for (int i = 0; i < NKT; i++) {
        CP_WAIT(NSTG - 2);
        __syncthreads();

        int j = i + NSTG - 1;
        if (j < NKT) {
            uint32_t ab = sbase + (j % NSTG) * STG_BYTES;
            fill_stage(ab, ab + A_BYTES, rowbase, colbase, j * BKB, tid);
        }
        CP_COMMIT();

        const uint32_t aB = sbase + (i % NSTG) * STG_BYTES;
        const uint32_t bB = aB + A_BYTES;
        #pragma unroll
        for (int s = 0; s < 4; s++) {            // each s = 32 int8 k-elems
            uint32_t af[4][4];
            #pragma unroll
            for (int x = 0; x < 4; x++)
                ldsm4(af[x][0], af[x][1], af[x][2], af[x][3],
                      aB + a_off[x] + (uint32_t)(((((s << 1) | a_c)) ^ a_x7) << 4));
            uint32_t bf[8][2];
            #pragma unroll
            for (int jp = 0; jp < 4; jp++)
                ldsm4(bf[2*jp][0], bf[2*jp][1], bf[2*jp+1][0], bf[2*jp+1][1],
                      bB + b_off[jp] + (uint32_t)(((((s << 1) | b_c)) ^ b_x7) << 4));
            #pragma unroll
            for (int x = 0; x < 4; x++)
                #pragma unroll
                for (int j2 = 0; j2 < 8; j2++)
                    MMA16832S8(acc[x][j2], af[x], bf[j2]);
        }
    }

    // epilogue: s32 stores (thread map: row=lane/4(+8), col=2*(lane%4)+{0,1})
    const int tr = lane >> 2;
    const int tc = (lane & 3) * 2;
    #pragma unroll
    for (int x = 0; x < 4; x++) {
        size_t row0 = (size_t)(rowbase + warp_m * 64 + x * 16 + tr);
        #pragma unroll
        for (int j2 = 0; j2 < 8; j2++) {
            int col = colbase + warp_n * 64 + j2 * 8 + tc;
            *(int2*)(g_simi + row0 * VOCAB + col) = make_int2(acc[x][j2][0], acc[x][j2][1]);
            *(int2*)(g_simi + (row0 + 8) * VOCAB + col) = make_int2(acc[x][j2][2], acc[x][j2][3]);
        }
    }
}

// ---------------- top-32 candidates per row (exact on s32 sims) -------------
__global__ void __launch_bounds__(256) topm_kernel() {
    int row = blockIdx.x;
    int tid = threadIdx.x;
    const int4* s4 = (const int4*)(g_simi + (size_t)row * VOCAB);

    int lv[LOCK], li[LOCK];
    #pragma unroll
    for (int i = 0; i < LOCK; i++) { lv[i] = INT32_MIN; li[i] = -1; }

    for (int j = tid; j < VOCAB / 4; j += 256) {
        int4 v = s4[j];
        int vals[4] = {v.x, v.y, v.z, v.w};
        #pragma unroll
        for (int l = 0; l < 4; l++) {
            int vv = vals[l];
            if (vv > lv[LOCK - 1]) {
                lv[LOCK - 1] = vv; li[LOCK - 1] = 4 * j + l;
                #pragma unroll
                for (int p = LOCK - 1; p > 0; p--) {
                    if (lv[p] > lv[p - 1]) {
                        int tv = lv[p]; lv[p] = lv[p - 1]; lv[p - 1] = tv;
                        int ti = li[p]; li[p] = li[p - 1]; li[p - 1] = ti;
                    }
                }
            }
        }
    }

    __shared__ int sv[256 * LOCK];
    __shared__ int si[256 * LOCK];
    #pragma unroll
    for (int i = 0; i < LOCK; i++) { sv[tid * LOCK + i] = lv[i]; si[tid * LOCK + i] = li[i]; }
    __syncthreads();

    __shared__ int bv[256];
    __shared__ int bvi[256];
    __shared__ int bo[256];
    for (int k = 0; k < CAND; k++) {
        int best = INT32_MIN; int bi = 0x7fffffff; int bofs = 0;
        #pragma unroll
        for (int i = 0; i < LOCK; i++) {
            int e = tid * LOCK + i;
            int v = sv[e]; int ii = si[e];
            if (v > best || (v == best && ii >= 0 && ii < bi)) { best = v; bi = ii; bofs = e; }
        }
        bv[tid] = best; bvi[tid] = bi; bo[tid] = bofs;
        __syncthreads();
        for (int o = 128; o > 0; o >>= 1) {
            if (tid < o) {
                if (bv[tid + o] > bv[tid] ||
                    (bv[tid + o] == bv[tid] && bvi[tid + o] < bvi[tid])) {
                    bv[tid] = bv[tid + o]; bvi[tid] = bvi[tid + o]; bo[tid] = bo[tid + o];
                }
            }
            __syncthreads();
        }
        if (tid == 0) {
            g_cand[row * CAND + k] = bvi[0];
            sv[bo[0]] = INT32_MIN;
        }
        __syncthreads();
    }
}

// ---------------- exact fp32 rescore + softmax + projection -----------------
__global__ void __launch_bounds__(256) rescore_out_kernel(
    const float* __restrict__ emb, const float* __restrict__ voc,
    float* __restrict__ out)
{
    int row  = blockIdx.x;
    int tid  = threadIdx.x;
    int lane = tid & 31;
    int wid  = tid >> 5;

    __shared__ float semb[DIM];
    const float4* e4 = (const float4*)(emb + (size_t)row * DIM);
    float4* s4 = (float4*)semb;
    for (int q = tid; q < DIM / 4; q += 256) s4[q] = e4[q];

    __shared__ int   cidx[CAND];
    __shared__ float csim[CAND];
    if (tid < CAND) cidx[tid] = g_cand[row * CAND + tid];
    __syncthreads();

    float inv_e = g_emb_inv[row];
    #pragma unroll
    for (int s = 0; s < 4; s++) {
        int c = wid * 4 + s;
        int v = cidx[c];
        const float4* vr = (const float4*)(voc + (size_t)v * DIM);
        float acc = 0.0f;
        for (int d = lane; d < DIM / 4; d += 32) {
            float4 a = s4[d];
            float4 b = vr[d];
            acc += a.x * b.x + a.y * b.y + a.z * b.z + a.w * b.w;
        }
        #pragma unroll
        for (int o = 16; o > 0; o >>= 1) acc += __shfl_xor_sync(0xffffffffu, acc, o);
        if (lane == 0) csim[c] = acc * inv_e * g_voc_inv[v];
    }
    __syncthreads();

    __shared__ float w5[TOPK];
    __shared__ int   i5[TOPK];
    if (tid == 0) {
        bool used[CAND];
        #pragma unroll
        for (int j = 0; j < CAND; j++) used[j] = false;
        float sv5[TOPK];
        for (int k = 0; k < TOPK; k++) {
            float best = -1e30f; int bj = -1; int bvix = 0x7fffffff;
            for (int j = 0; j < CAND; j++) {
                if (used[j]) continue;
                float v = csim[j]; int vi = cidx[j];
                if (v > best || (v == best && vi < bvix)) { best = v; bj = j; bvix = vi; }
            }
            used[bj] = true; sv5[k] = best; i5[k] = bvix;
        }
        float mx = sv5[0];
        float es[TOPK], sum = 0.0f;
        #pragma unroll
        for (int k = 0; k < TOPK; k++) { es[k] = expf((sv5[k] - mx) * TEMP); sum += es[k]; }
        #pragma unroll
        for (int k = 0; k < TOPK; k++) w5[k] = es[k] / sum;
    }
    __syncthreads();

    const float4* v0 = (const float4*)(voc + (size_t)i5[0] * DIM);
    const float4* v1 = (const float4*)(voc + (size_t)i5[1] * DIM);
    const float4* v2 = (const float4*)(voc + (size_t)i5[2] * DIM);
    const float4* v3 = (const float4*)(voc + (size_t)i5[3] * DIM);
    const float4* v4 = (const float4*)(voc + (size_t)i5[4] * DIM);
    float w0 = w5[0], w1 = w5[1], w2 = w5[2], w3 = w5[3], w4 = w5[4];
    float4* o4 = (float4*)(out + (size_t)row * DIM);

    for (int q = tid; q < DIM / 4; q += 256) {
        float4 e = s4[q];
        float4 a = v0[q], b = v1[q], c = v2[q], d = v3[q], f = v4[q];
        float4 r;
        r.x = ALPHA * e.x + (1.0f - ALPHA) * (w0 * a.x + w1 * b.x + w2 * c.x + w3 * d.x + w4 * f.x);
        r.y = ALPHA * e.y + (1.0f - ALPHA) * (w0 * a.y + w1 * b.y + w2 * c.y + w3 * d.y + w4 * f.y);
        r.z = ALPHA * e.z + (1.0f - ALPHA) * (w0 * a.z + w1 * b.z + w2 * c.z + w3 * d.z + w4 * f.z);
        r.w = ALPHA * e.w + (1.0f - ALPHA) * (w0 * a.w + w1 * b.w + w2 * c.w + w3 * d.w + w4 * f.w);
        o4[q] = r;
    }
}

// ---------------- launch -----------------------------------------------------
extern "C" void kernel_launch(void* const* d_in, const int* in_sizes, int n_in,
                              void* d_out, int out_size) {
    const float* emb = (const float*)d_in[0];
    const float* voc = (const float*)d_in[1];
    if (in_sizes[0] != NROWS * DIM) {
        emb = (const float*)d_in[1];
        voc = (const float*)d_in[0];
    }
    float* out = (float*)d_out;

    prep_emb_kernel<<<NROWS, 256>>>(emb);
    prep_voc_kernel<<<VOCAB, 256>>>(voc);

    cudaFuncSetAttribute(sim_gemm_kernel,
                         cudaFuncAttributeMaxDynamicSharedMemorySize, GEMM_SMEM);
    dim3 grid(NROWS / BM, VOCAB / BN);   // rows-fastest: B tile L2 reuse
    sim_gemm_kernel<<<grid, 256, GEMM_SMEM>>>();

    topm_kernel<<<NROWS, 256>>>();
    rescore_out_kernel<<<NROWS, 256>>>(emb, voc, out);
}

// round 7
// speedup vs baseline: 2.9602x; 2.0139x over previous
#include <cuda_runtime.h>
#include <cuda_fp16.h>
#include <cstdint>

#define NROWS 8192
#define DIM   2048
#define VOCAB 32000
#define TOPK  5
#define CAND  16
#define LOCK  8
#define ALPHA 0.5f
#define TEMP  10.0f

// GEMM tiling (f16): CTA 128x256, k-tile 64 halfs (=128B rows)
#define BM    128
#define BN    256
#define BK    64
#define NKT   (DIM / BK)            // 32
#define NSTG  4
#define A_BYTES (BM * 128)
#define B_BYTES (BN * 128)
#define STG_BYTES (A_BYTES + B_BYTES)
#define GEMM_SMEM (NSTG * STG_BYTES)   // 192 KB

// ---------------- device scratch ----------------
__device__ __half g_embh[(size_t)NROWS * DIM];
__device__ __half g_voch[(size_t)VOCAB * DIM];     // vocab * inv_norm
__device__ __half g_simh[(size_t)NROWS * VOCAB];   // f16 screen sims
__device__ float  g_emb_inv[NROWS];
__device__ float  g_voc_inv[VOCAB];
__device__ int    g_cand[NROWS * CAND];

// ---------------- helpers ----------------
__device__ __forceinline__ uint32_t smem_u32(const void* p) {
    uint32_t a;
    asm("{ .reg .u64 t; cvta.to.shared.u64 t, %1; cvt.u32.u64 %0, t; }" : "=r"(a) : "l"(p));
    return a;
}
#define CP16(dst_u32, src_ptr) \
    asm volatile("cp.async.cg.shared.global [%0], [%1], 16;" \
        :: "r"(dst_u32), "l"((unsigned long long)__cvta_generic_to_global((const void*)(src_ptr))) : "memory")
#define CP_COMMIT() asm volatile("cp.async.commit_group;" ::: "memory")
#define CP_WAIT(n)  asm volatile("cp.async.wait_group %0;" :: "n"(n) : "memory")

__device__ __forceinline__ void ldsm4(uint32_t& d0, uint32_t& d1, uint32_t& d2, uint32_t& d3,
                                      uint32_t addr) {
    asm volatile("ldmatrix.sync.aligned.m8n8.x4.shared.b16 {%0,%1,%2,%3}, [%4];"
                 : "=r"(d0), "=r"(d1), "=r"(d2), "=r"(d3) : "r"(addr));
}
// f16 inputs, f16 accumulate: D,C = 2 regs (4 halves)
#define MMA16816F16(d, a, b) \
    asm volatile("mma.sync.aligned.m16n8k16.row.col.f16.f16.f16.f16 " \
        "{%0,%1}, {%2,%3,%4,%5}, {%6,%7}, {%0,%1};" \
        : "+r"((d)[0]), "+r"((d)[1]) \
        : "r"((a)[0]), "r"((a)[1]), "r"((a)[2]), "r"((a)[3]), "r"((b)[0]), "r"((b)[1]))

// ---------------- prep: norms + f16 conversion -------------------------------
__global__ void __launch_bounds__(256) prep_emb_kernel(const float* __restrict__ emb) {
    int row = blockIdx.x;
    int t = threadIdx.x;
    const float4* s4 = (const float4*)(emb + (size_t)row * DIM);
    float4 a = s4[t * 2], b = s4[t * 2 + 1];
    float ss = a.x*a.x + a.y*a.y + a.z*a.z + a.w*a.w
             + b.x*b.x + b.y*b.y + b.z*b.z + b.w*b.w;
    __shared__ float red[256];
    red[t] = ss; __syncthreads();
    for (int o = 128; o > 0; o >>= 1) { if (t < o) red[t] += red[t + o]; __syncthreads(); }
    if (t == 0) g_emb_inv[row] = 1.0f / fmaxf(sqrtf(red[0]), 1e-12f);
    uint4 pk;
    ((__half2*)&pk)[0] = __floats2half2_rn(a.x, a.y);
    ((__half2*)&pk)[1] = __floats2half2_rn(a.z, a.w);
    ((__half2*)&pk)[2] = __floats2half2_rn(b.x, b.y);
    ((__half2*)&pk)[3] = __floats2half2_rn(b.z, b.w);
    *(uint4*)(g_embh + (size_t)row * DIM + t * 8) = pk;
}

__global__ void __launch_bounds__(256) prep_voc_kernel(const float* __restrict__ voc) {
    int row = blockIdx.x;
    int t = threadIdx.x;
    const float4* s4 = (const float4*)(voc + (size_t)row * DIM);
    float4 a = s4[t * 2], b = s4[t * 2 + 1];
    float ss = a.x*a.x + a.y*a.y + a.z*a.z + a.w*a.w
             + b.x*b.x + b.y*b.y + b.z*b.z + b.w*b.w;
    __shared__ float red[256];
    __shared__ float s_inv;
    red[t] = ss; __syncthreads();
    for (int o = 128; o > 0; o >>= 1) { if (t < o) red[t] += red[t + o]; __syncthreads(); }
    if (t == 0) {
        float inv = 1.0f / fmaxf(sqrtf(red[0]), 1e-12f);
        g_voc_inv[row] = inv;
        s_inv = inv;
    }
    __syncthreads();
    float inv = s_inv;
    uint4 pk;
    ((__half2*)&pk)[0] = __floats2half2_rn(a.x * inv, a.y * inv);
    ((__half2*)&pk)[1] = __floats2half2_rn(a.z * inv, a.w * inv);
    ((__half2*)&pk)[2] = __floats2half2_rn(b.x * inv, b.y * inv);
    ((__half2*)&pk)[3] = __floats2half2_rn(b.z * inv, b.w * inv);
    *(uint4*)(g_voch + (size_t)row * DIM + t * 8) = pk;
}

// ---------------- f16 screen GEMM: g_simh = embh @ voch^T -------------------
__device__ __forceinline__ void fill_stage(uint32_t a_u32, uint32_t b_u32,
                                           int rowbase, int colbase, int kt, int tid) {
    #pragma unroll
    for (int q = 0; q < 4; q++) {                // A: 1024 x 16B chunks
        int idx = tid + q * 256;
        int r = idx >> 3, c = idx & 7;
        uint32_t dst = a_u32 + (uint32_t)(r * 128 + ((c ^ (r & 7)) << 4));
        CP16(dst, g_embh + (size_t)(rowbase + r) * DIM + kt + c * 8);
    }
    #pragma unroll
    for (int q = 0; q < 8; q++) {                // B: 2048 x 16B chunks
        int idx = tid + q * 256;
        int r = idx >> 3, c = idx & 7;
        uint32_t dst = b_u32 + (uint32_t)(r * 128 + ((c ^ (r & 7)) << 4));
        CP16(dst, g_voch + (size_t)(colbase + r) * DIM + kt + c * 8);
    }
}

__global__ void __launch_bounds__(256, 1) sim_gemm_kernel() {
    extern __shared__ __align__(128) char sm[];
    const uint32_t sbase = smem_u32(sm);
    const int tid  = threadIdx.x;
    const int lane = tid & 31;
    const int wid  = tid >> 5;
    const int warp_m = wid >> 2;
    const int warp_n = wid & 3;
    const int rowbase = blockIdx.x * BM;
    const int colbase = blockIdx.y * BN;

    const int a_r  = lane & 15;
    const int a_c  = lane >> 4;
    const int a_x7 = a_r & 7;
    uint32_t a_off[4];
    #pragma unroll
    for (int x = 0; x < 4; x++)
        a_off[x] = (uint32_t)((warp_m * 64 + x * 16 + a_r) * 128);

    const int b_q  = lane >> 3;
    const int b_nl = ((b_q >> 1) << 3) | (lane & 7);
    const int b_c  = b_q & 1;
    const int b_x7 = lane & 7;
    uint32_t b_off[4];
    #pragma unroll
    for (int jp = 0; jp < 4; jp++)
        b_off[jp] = (uint32_t)((warp_n * 64 + jp * 16 + b_nl) * 128);

    uint32_t acc[4][8][2];
    #pragma unroll
    for (int x = 0; x < 4; x++)
        #pragma unroll
        for (int j = 0; j < 8; j++)
            { acc[x][j][0] = 0u; acc[x][j][1] = 0u; }

    #pragma unroll
    for (int p = 0; p < NSTG - 1; p++) {
        uint32_t ab = sbase + p * STG_BYTES;
        fill_stage(ab, ab + A_BYTES, rowbase, colbase, p * BK, tid);
        CP_COMMIT();
    }

    for (int i = 0; i < NKT; i++) {
        CP_WAIT(NSTG - 2);
        __syncthreads();

        int j = i + NSTG - 1;
        if (j < NKT) {
            uint32_t ab = sbase + (j % NSTG) * STG_BYTES;
            fill_stage(ab, ab + A_BYTES, rowbase, colbase, j * BK, tid);
        }
        CP_COMMIT();

        const uint32_t aB = sbase + (i % NSTG) * STG_BYTES;
        const uint32_t bB = aB + A_BYTES;
        #pragma unroll
        for (int s = 0; s < 4; s++) {            // each s = 16 f16 k-elems
            uint32_t af[4][4];
            #pragma unroll
            for (int x = 0; x < 4; x++)
                ldsm4(af[x][0], af[x][1], af[x][2], af[x][3],
                      aB + a_off[x] + (uint32_t)(((((s << 1) | a_c)) ^ a_x7) << 4));
            uint32_t bf[8][2];
            #pragma unroll
            for (int jp = 0; jp < 4; jp++)
                ldsm4(bf[2*jp][0], bf[2*jp][1], bf[2*jp+1][0], bf[2*jp+1][1],
                      bB + b_off[jp] + (uint32_t)(((((s << 1) | b_c)) ^ b_x7) << 4));
            #pragma unroll
            for (int x = 0; x < 4; x++)
                #pragma unroll
                for (int j2 = 0; j2 < 8; j2++)
                    MMA16816F16(acc[x][j2], af[x], bf[j2]);
        }
    }

    // epilogue: each acc reg is a half2 {col tc, tc+1}; reg0=row tr, reg1=row tr+8
    const int tr = lane >> 2;
    const int tc = (lane & 3) * 2;
    #pragma unroll
    for (int x = 0; x < 4; x++) {
        size_t row0 = (size_t)(rowbase + warp_m * 64 + x * 16 + tr);
        #pragma unroll
        for (int j2 = 0; j2 < 8; j2++) {
            int col = colbase + warp_n * 64 + j2 * 8 + tc;
            *(uint32_t*)(g_simh + row0 * VOCAB + col) = acc[x][j2][0];
            *(uint32_t*)(g_simh + (row0 + 8) * VOCAB + col) = acc[x][j2][1];
        }
    }
}

// ---------------- top-16 candidates per row (f16 sims, hmax2 prefilter) -----
__global__ void __launch_bounds__(256) topm_kernel() {
    int row = blockIdx.x;
    int tid = threadIdx.x;
    int lane = tid & 31;
    int wid  = tid >> 5;
    const uint4* s16 = (const uint4*)(g_simh + (size_t)row * VOCAB);

    float lv[LOCK];
    int   li[LOCK];
    #pragma unroll
    for (int i = 0; i < LOCK; i++) { lv[i] = -3e38f; li[i] = -1; }
    __half thr_h = __float2half_rn(-65504.0f);

    for (int c = tid; c < VOCAB / 8; c += 256) {
        uint4 w = s16[c];
        __half2 p0 = *(__half2*)&w.x, p1 = *(__half2*)&w.y;
        __half2 p2 = *(__half2*)&w.z, p3 = *(__half2*)&w.w;
        __half2 m2 = __hmax2(__hmax2(p0, p1), __hmax2(p2, p3));
        __half mm = __hmax(__low2half(m2), __high2half(m2));
        if (__hgt(mm, thr_h)) {
            float vals[8];
            vals[0] = __half2float(__low2half(p0)); vals[1] = __half2float(__high2half(p0));
            vals[2] = __half2float(__low2half(p1)); vals[3] = __half2float(__high2half(p1));
            vals[4] = __half2float(__low2half(p2)); vals[5] = __half2float(__high2half(p2));
            vals[6] = __half2float(__low2half(p3)); vals[7] = __half2float(__high2half(p3));
            #pragma unroll
            for (int l = 0; l < 8; l++) {
                float v = vals[l];
                if (v > lv[LOCK - 1]) {
                    lv[LOCK - 1] = v; li[LOCK - 1] = c * 8 + l;
                    #pragma unroll
                    for (int p = LOCK - 1; p > 0; p--) {
                        if (lv[p] > lv[p - 1]) {
                            float tv = lv[p]; lv[p] = lv[p - 1]; lv[p - 1] = tv;
                            int ti = li[p]; li[p] = li[p - 1]; li[p - 1] = ti;
                        }
                    }
                }
            }
            thr_h = __float2half_rn(lv[LOCK - 1]);   // exact: lv came from a half
        }
    }

    // merge 256 sorted 8-lists -> global top-16 via head tournament
    __shared__ float swv[8];
    __shared__ int   swi[8];
    __shared__ int   s_winIdx;
    float hval = lv[0];
    int   hidx = li[0];
    int   pos  = 0;

    for (int k = 0; k < CAND; k++) {
        float v = hval; int ix = hidx;
        #pragma unroll
        for (int o = 16; o > 0; o >>= 1) {
            float v2 = __shfl_xor_sync(0xffffffffu, v, o);
            int   i2 = __shfl_xor_sync(0xffffffffu, ix, o);
            if (v2 > v || (v2 == v && i2 != -1 && (unsigned)i2 < (unsigned)ix)) { v = v2; ix = i2; }
        }
        if (lane == 0) { swv[wid] = v; swi[wid] = ix; }
        __syncthreads();
        if (tid == 0) {
            float bv = swv[0]; int bi = swi[0];
            #pragma unroll
            for (int wq = 1; wq < 8; wq++) {
                if (swv[wq] > bv || (swv[wq] == bv && swi[wq] != -1 && (unsigned)swi[wq] < (unsigned)bi)) {
                    bv = swv[wq]; bi = swi[wq];
                }
            }
            g_cand[row * CAND + k] = bi;
            s_winIdx = bi;
        }
        __syncthreads();
        int winIdx = s_winIdx;
        if (hidx == winIdx && hidx != -1) {
            pos++;
            hval = (pos < LOCK) ? lv[pos] : -3e38f;
            hidx = (pos < LOCK) ? li[pos] : -1;
        }
        __syncthreads();
    }
}

// ---------------- exact fp32 rescore + softmax + projection -----------------
__global__ void __launch_bounds__(256) rescore_out_kernel(
    const float* __restrict__ emb, const float* __restrict__ voc,
    float* __restrict__ out)
{
    int row  = blockIdx.x;
    int tid  = threadIdx.x;
    int lane = tid & 31;
    int wid  = tid >> 5;

    __shared__ float semb[DIM];
    const float4* e4 = (const float4*)(emb + (size_t)row * DIM);
    float4* s4 = (float4*)semb;
    for (int q = tid; q < DIM / 4; q += 256) s4[q] = e4[q];

    __shared__ int   cidx[CAND];
    __shared__ float csim[CAND];
    if (tid < CAND) cidx[tid] = g_cand[row * CAND + tid];
    __syncthreads();

    float inv_e = g_emb_inv[row];
    #pragma unroll
    for (int s = 0; s < 2; s++) {
        int c = wid * 2 + s;
        int v = cidx[c];
        const float4* vr = (const float4*)(voc + (size_t)v * DIM);
        float acc = 0.0f;
        for (int d = lane; d < DIM / 4; d += 32) {
            float4 a = s4[d];
            float4 b = vr[d];
            acc += a.x * b.x + a.y * b.y + a.z * b.z + a.w * b.w;
        }
        #pragma unroll
        for (int o = 16; o > 0; o >>= 1) acc += __shfl_xor_sync(0xffffffffu, acc, o);
        if (lane == 0) csim[c] = acc * inv_e * g_voc_inv[v];
    }
    __syncthreads();

    __shared__ float w5[TOPK];
    __shared__ int   i5[TOPK];
    if (tid == 0) {
        bool used[CAND];
        #pragma unroll
        for (int j = 0; j < CAND; j++) used[j] = false;
        float sv5[TOPK];
        for (int k = 0; k < TOPK; k++) {
            float best = -1e30f; int bj = -1; int bvix = 0x7fffffff;
            for (int j = 0; j < CAND; j++) {
                if (used[j]) continue;
                float v = csim[j]; int vi = cidx[j];
                if (v > best || (v == best && vi < bvix)) { best = v; bj = j; bvix = vi; }
            }
            used[bj] = true; sv5[k] = best; i5[k] = bvix;
        }
        float mx = sv5[0];
        float es[TOPK], sum = 0.0f;
        #pragma unroll
        for (int k = 0; k < TOPK; k++) { es[k] = expf((sv5[k] - mx) * TEMP); sum += es[k]; }
        #pragma unroll
        for (int k = 0; k < TOPK; k++) w5[k] = es[k] / sum;
    }
    __syncthreads();

    const float4* v0 = (const float4*)(voc + (size_t)i5[0] * DIM);
    const float4* v1 = (const float4*)(voc + (size_t)i5[1] * DIM);
    const float4* v2 = (const float4*)(voc + (size_t)i5[2] * DIM);
    const float4* v3 = (const float4*)(voc + (size_t)i5[3] * DIM);
    const float4* v4 = (const float4*)(voc + (size_t)i5[4] * DIM);
    float w0 = w5[0], w1 = w5[1], w2 = w5[2], w3 = w5[3], w4 = w5[4];
    float4* o4 = (float4*)(out + (size_t)row * DIM);

    for (int q = tid; q < DIM / 4; q += 256) {
        float4 e = s4[q];
        float4 a = v0[q], b = v1[q], c = v2[q], d = v3[q], f = v4[q];
        float4 r;
        r.x = ALPHA * e.x + (1.0f - ALPHA) * (w0 * a.x + w1 * b.x + w2 * c.x + w3 * d.x + w4 * f.x);
        r.y = ALPHA * e.y + (1.0f - ALPHA) * (w0 * a.y + w1 * b.y + w2 * c.y + w3 * d.y + w4 * f.y);
        r.z = ALPHA * e.z + (1.0f - ALPHA) * (w0 * a.z + w1 * b.z + w2 * c.z + w3 * d.z + w4 * f.z);
        r.w = ALPHA * e.w + (1.0f - ALPHA) * (w0 * a.w + w1 * b.w + w2 * c.w + w3 * d.w + w4 * f.w);
        o4[q] = r;
    }
}

// ---------------- launch -----------------------------------------------------
extern "C" void kernel_launch(void* const* d_in, const int* in_sizes, int n_in,
                              void* d_out, int out_size) {
    const float* emb = (const float*)d_in[0];
    const float* voc = (const float*)d_in[1];
    if (in_sizes[0] != NROWS * DIM) {
        emb = (const float*)d_in[1];
        voc = (const float*)d_in[0];
    }
    float* out = (float*)d_out;

    prep_emb_kernel<<<NROWS, 256>>>(emb);
    prep_voc_kernel<<<VOCAB, 256>>>(voc);

    cudaFuncSetAttribute(sim_gemm_kernel,
                         cudaFuncAttributeMaxDynamicSharedMemorySize, GEMM_SMEM);
    dim3 grid(NROWS / BM, VOCAB / BN);   // rows-fastest: B tile L2 reuse
    sim_gemm_kernel<<<grid, 256, GEMM_SMEM>>>();

    topm_kernel<<<NROWS, 256>>>();
    rescore_out_kernel<<<NROWS, 256>>>(emb, voc, out);
}